// round 8
// baseline (speedup 1.0000x reference)
#include <cuda_runtime.h>
#include <math.h>
#include <stdint.h>

// ChamferLoss via exact pruned NN, v5: sort/scan decoupled through global
// staging so scan runs as 512 small independent co-resident blocks.
// batch=64, k=2048 2-D points (x = cols [0,2048), y = cols [2048,4096)).
// Exactness: every query's min is taken over a proven covering superset of
// the true-NN witnesses (x-window vote bound), so results are bitwise equal
// to brute force regardless of within-bucket scatter order. Determinism:
// per-query results stored by original index; reduction order fixed by code.

#define K        2048
#define BATCH    64
#define NBINS    128
#define NTASKS   (2 * BATCH)        // (batch, direction) pairs
#define SORT_T   256
#define SCAN_T   256
#define PARTS    4                  // scan blocks per task
#define NSCAN    (NTASKS * PARTS)   // 512 scan blocks
#define PPT      (K / SORT_T)       // 8 points per thread per side (sort)

__device__ float4 g_sortedD[NTASKS][K];        // (x, y, x^2+y^2, 0)   4 MB
__device__ float2 g_sortedQ[NTASKS][K];        //                      2 MB
__device__ short  g_qidx   [NTASKS][K];        // original index     0.5 MB
__device__ int    g_offD   [NTASKS][NBINS + 1];
__device__ float  g_params [NTASKS][2];        // xmin, inv
__device__ float  g_rslt   [NTASKS][K];        // per-query NN dist    1 MB
__device__ float  g_partials[NTASKS];
__device__ unsigned int g_count = 0;

// ---------------------------------------------------------------------------
// Kernel 1: per-task counting sort of both sides by x into global staging.
// ---------------------------------------------------------------------------
__global__ __launch_bounds__(SORT_T)
void sort_kernel(const float* __restrict__ pred,
                 const float* __restrict__ targ)
{
    const int bx    = blockIdx.x;
    const int batch = bx >> 1;
    const int dir   = bx & 1;
    const int tid   = threadIdx.x;
    const int wg    = tid >> 5, lane = tid & 31;

    const float* q_base = (dir == 0 ? pred : targ) + batch * (2 * K);
    const float* d_base = (dir == 0 ? targ : pred) + batch * (2 * K);

    __shared__ int   cntD[NBINS], cntQ[NBINS];
    __shared__ float redA[SORT_T / 32], redB[SORT_T / 32];

    float Dx[PPT], Dy[PPT], Qx[PPT], Qy[PPT];
    float lmin = INFINITY, lmax = -INFINITY;
    #pragma unroll
    for (int r = 0; r < PPT; ++r) {
        int j = r * SORT_T + tid;
        Dx[r] = d_base[j];  Dy[r] = d_base[j + K];
        Qx[r] = q_base[j];  Qy[r] = q_base[j + K];
        lmin = fminf(lmin, fminf(Dx[r], Qx[r]));
        lmax = fmaxf(lmax, fmaxf(Dx[r], Qx[r]));
    }
    #pragma unroll
    for (int o = 16; o > 0; o >>= 1) {
        lmin = fminf(lmin, __shfl_xor_sync(0xFFFFFFFF, lmin, o));
        lmax = fmaxf(lmax, __shfl_xor_sync(0xFFFFFFFF, lmax, o));
    }
    if (lane == 0) { redA[wg] = lmin; redB[wg] = lmax; }
    __syncthreads();
    if (tid < 32) {
        float a = (tid < SORT_T / 32) ? redA[tid] : INFINITY;
        float b = (tid < SORT_T / 32) ? redB[tid] : -INFINITY;
        #pragma unroll
        for (int o = 4; o > 0; o >>= 1) {
            a = fminf(a, __shfl_xor_sync(0xFFFFFFFF, a, o));
            b = fmaxf(b, __shfl_xor_sync(0xFFFFFFFF, b, o));
        }
        if (tid == 0) { redA[0] = a; redB[0] = b; }
    }
    __syncthreads();
    const float xmin = redA[0];
    const float inv  = (float)NBINS / ((redB[0] - xmin) * 1.000001f + 1e-30f);

    if (tid < NBINS) { cntD[tid] = 0; cntQ[tid] = 0; }
    __syncthreads();

    int bD[PPT], bQ[PPT];
    #pragma unroll
    for (int r = 0; r < PPT; ++r) {
        bD[r] = min(NBINS - 1, max(0, (int)((Dx[r] - xmin) * inv)));
        atomicAdd(&cntD[bD[r]], 1);
        bQ[r] = min(NBINS - 1, max(0, (int)((Qx[r] - xmin) * inv)));
        atomicAdd(&cntQ[bQ[r]], 1);
    }
    __syncthreads();

    // Exclusive prefix: warp 0 -> D (also writes g_offD), warp 1 -> Q.
    if (wg < 2) {
        int* cnt = (wg == 0) ? cntD : cntQ;
        int c0 = cnt[lane * 4 + 0], c1 = cnt[lane * 4 + 1];
        int c2 = cnt[lane * 4 + 2], c3 = cnt[lane * 4 + 3];
        int s = c0 + c1 + c2 + c3, e = s;
        #pragma unroll
        for (int o = 1; o < 32; o <<= 1) {
            int n = __shfl_up_sync(0xFFFFFFFF, e, o);
            if (lane >= o) e += n;
        }
        int excl = e - s;
        if (wg == 0) {
            g_offD[bx][lane * 4 + 0] = excl;
            g_offD[bx][lane * 4 + 1] = excl + c0;
            g_offD[bx][lane * 4 + 2] = excl + c0 + c1;
            g_offD[bx][lane * 4 + 3] = excl + c0 + c1 + c2;
            if (lane == 31) g_offD[bx][NBINS] = e;
        }
        cnt[lane * 4 + 0] = excl;
        cnt[lane * 4 + 1] = excl + c0;
        cnt[lane * 4 + 2] = excl + c0 + c1;
        cnt[lane * 4 + 3] = excl + c0 + c1 + c2;
    }
    __syncthreads();

    #pragma unroll
    for (int r = 0; r < PPT; ++r) {
        int p = atomicAdd(&cntD[bD[r]], 1);
        g_sortedD[bx][p] = make_float4(Dx[r], Dy[r],
                                       fmaf(Dx[r], Dx[r], Dy[r] * Dy[r]), 0.0f);
        p = atomicAdd(&cntQ[bQ[r]], 1);
        g_sortedQ[bx][p] = make_float2(Qx[r], Qy[r]);
        g_qidx[bx][p]    = (short)(r * SORT_T + tid);
    }
    if (tid == 0) { g_params[bx][0] = xmin; g_params[bx][1] = inv; }
}

// ---------------------------------------------------------------------------
// Kernel 2: scan. 4 blocks per task; each block = 8 warps x 64 queries.
// ---------------------------------------------------------------------------
__global__ __launch_bounds__(SCAN_T, 4)
void scan_kernel()
{
    __shared__ float4 shD[K];            // 32 KB sorted DB tile
    __shared__ int    offD[NBINS + 1];

    const int task = blockIdx.x >> 2;
    const int part = blockIdx.x & 3;
    const int tid  = threadIdx.x;
    const int wg   = tid >> 5, lane = tid & 31;

    #pragma unroll
    for (int r = 0; r < K / SCAN_T; ++r)
        shD[r * SCAN_T + tid] = g_sortedD[task][r * SCAN_T + tid];
    if (tid <= NBINS) offD[tid] = g_offD[task][tid];
    const float xmin = g_params[task][0];
    const float inv  = g_params[task][1];
    const float w    = 1.0f / inv;
    __syncthreads();

    // This warp's 64 queries (2 per lane), pair-packed load.
    const int pairidx = part * (K / 2 / PARTS) + wg * 32 + lane;
    const float4 qq = *(const float4*)&g_sortedQ[task][2 * pairidx];
    const short2 qi = ((const short2*)g_qidx[task])[pairidx];

    const float ax0 = -2.0f * qq.x, ay0 = -2.0f * qq.y;
    const float ax1 = -2.0f * qq.z, ay1 = -2.0f * qq.w;
    const float q20 = fmaf(qq.x, qq.x, qq.y * qq.y);
    const float q21 = fmaf(qq.z, qq.z, qq.w * qq.w);
    const float qxmn = fminf(qq.x, qq.z);
    const float qxmx = fmaxf(qq.x, qq.z);

    int b0 = min(NBINS - 1, max(0, (int)((qq.x - xmin) * inv)));
    int b1 = min(NBINS - 1, max(0, (int)((qq.z - xmin) * inv)));
    const int bl = __reduce_min_sync(0xFFFFFFFF, min(b0, b1));
    const int bh = __reduce_max_sync(0xFFFFFFFF, max(b0, b1));

    float mnA0 = INFINITY, mnB0 = INFINITY;
    float mnA1 = INFINITY, mnB1 = INFINITY;

    // Phase 1: contiguous neighborhood (broadcast LDS.128, 2 queries/candidate)
    {
        const int lo = offD[max(bl - 1, 0)];
        const int hi = offD[min(bh + 1, NBINS - 1) + 1];
        int idx = lo;
        for (; idx + 2 <= hi; idx += 2) {
            float4 t0 = shD[idx], t1 = shD[idx + 1];
            mnA0 = fminf(mnA0, fmaf(ax0, t0.x, fmaf(ay0, t0.y, t0.z)));
            mnA1 = fminf(mnA1, fmaf(ax1, t0.x, fmaf(ay1, t0.y, t0.z)));
            mnB0 = fminf(mnB0, fmaf(ax0, t1.x, fmaf(ay0, t1.y, t1.z)));
            mnB1 = fminf(mnB1, fmaf(ax1, t1.x, fmaf(ay1, t1.y, t1.z)));
        }
        if (idx < hi) {
            float4 t = shD[idx];
            mnA0 = fminf(mnA0, fmaf(ax0, t.x, fmaf(ay0, t.y, t.z)));
            mnA1 = fminf(mnA1, fmaf(ax1, t.x, fmaf(ay1, t.y, t.z)));
        }
    }

    // Left expansion: one bucket at a time, warp vote to stop.
    for (int l = bl - 2; l >= 0; --l) {
        float best = fmaxf(q20 + fminf(mnA0, mnB0), q21 + fminf(mnA1, mnB1));
        float gap  = qxmn - (xmin + (float)(l + 1) * w);
        bool need  = (gap <= 0.0f) || (gap * gap < best);
        if (!__any_sync(0xFFFFFFFF, need)) break;
        const int lo = offD[l], hi = offD[l + 1];
        for (int idx = lo; idx < hi; ++idx) {
            float4 t = shD[idx];
            mnA0 = fminf(mnA0, fmaf(ax0, t.x, fmaf(ay0, t.y, t.z)));
            mnA1 = fminf(mnA1, fmaf(ax1, t.x, fmaf(ay1, t.y, t.z)));
        }
    }
    // Right expansion.
    for (int r = bh + 2; r < NBINS; ++r) {
        float best = fmaxf(q20 + fminf(mnA0, mnB0), q21 + fminf(mnA1, mnB1));
        float gap  = (xmin + (float)r * w) - qxmx;
        bool need  = (gap <= 0.0f) || (gap * gap < best);
        if (!__any_sync(0xFFFFFFFF, need)) break;
        const int lo = offD[r], hi = offD[r + 1];
        for (int idx = lo; idx < hi; ++idx) {
            float4 t = shD[idx];
            mnB0 = fminf(mnB0, fmaf(ax0, t.x, fmaf(ay0, t.y, t.z)));
            mnB1 = fminf(mnB1, fmaf(ax1, t.x, fmaf(ay1, t.y, t.z)));
        }
    }

    g_rslt[task][qi.x] = sqrtf(fmaxf(q20 + fminf(mnA0, mnB0), 0.0f));
    g_rslt[task][qi.y] = sqrtf(fmaxf(q21 + fminf(mnA1, mnB1), 0.0f));
}

// ---------------------------------------------------------------------------
// Kernel 3: deterministic fixed-order reduction + fused finalize.
// ---------------------------------------------------------------------------
__global__ __launch_bounds__(256)
void reduce_kernel(float* __restrict__ out)
{
    __shared__ float red[256];
    __shared__ int lastflag;
    const int t   = blockIdx.x;
    const int tid = threadIdx.x;

    float s = 0.0f;
    #pragma unroll
    for (int r = 0; r < K / 256; ++r)
        s += g_rslt[t][tid + r * 256];

    red[tid] = s; __syncthreads();
    for (int o = 128; o >= 32; o >>= 1) {
        if (tid < o) red[tid] += red[tid + o];
        __syncthreads();
    }
    float v = 0.0f;
    if (tid < 32) {
        v = red[tid];
        #pragma unroll
        for (int o = 16; o > 0; o >>= 1)
            v += __shfl_down_sync(0xFFFFFFFF, v, o);
    }
    if (tid == 0) {
        g_partials[t] = v;
        __threadfence();
        unsigned old = atomicAdd(&g_count, 1u);
        lastflag = (old == NTASKS - 1);
    }
    __syncthreads();
    if (lastflag && tid < 32) {
        volatile float* gp = g_partials;
        float acc = 0.0f;
        #pragma unroll
        for (int i = 0; i < NTASKS / 32; ++i)
            acc += gp[i * 32 + tid];
        #pragma unroll
        for (int o = 16; o > 0; o >>= 1)
            acc += __shfl_down_sync(0xFFFFFFFF, acc, o);
        if (tid == 0) {
            out[0] = acc * (1.0f / ((float)K * (float)BATCH));
            g_count = 0;   // reset for next graph replay
        }
    }
}

extern "C" void kernel_launch(void* const* d_in, const int* in_sizes, int n_in,
                              void* d_out, int out_size)
{
    const float* pred = (const float*)d_in[0];
    const float* targ = (const float*)d_in[1];
    float* out = (float*)d_out;

    sort_kernel<<<NTASKS, SORT_T>>>(pred, targ);
    scan_kernel<<<NSCAN, SCAN_T>>>();
    reduce_kernel<<<NTASKS, 256>>>(out);
}

// round 10
// speedup vs baseline: 1.1420x; 1.1420x over previous
#include <cuda_runtime.h>
#include <math.h>
#include <stdint.h>

// ChamferLoss via exact pruned NN, v6: fused kernel, 512 thr/block,
// heavy+light group pairing, fixed bucket range (no min/max prologue).
// batch=64, k=2048 2-D points (x = cols [0,2048), y = cols [2048,4096)).
// Exact: each query's min is over a proven covering superset (bucket-edge
// vote bound; clamped edge buckets keep one-sided containment), so results
// are bitwise equal to brute force regardless of scatter order.
// Deterministic: results by original index, fixed-order sums, fused finalize.

#define K        2048
#define BATCH    64
#define THREADS  512
#define NWARPS   16
#define PPT      4                  // points per thread per side
#define NBINS    256
#define NBLOCKS  (2 * BATCH)
#define XMIN     (-8.0f)
#define INVW     16.0f              // NBINS / 16
#define WB       0.0625f            // bucket width

#define SMEM_D_BYTES   (K * 16)     // float4: 32 KB
#define SMEM_Q_BYTES   (K * 8)      // float2: 16 KB
#define SMEM_QI_BYTES  (K * 2)      // short:   4 KB
#define DYN_SMEM       (SMEM_D_BYTES + SMEM_Q_BYTES + SMEM_QI_BYTES)

__device__ float g_partials[NBLOCKS];
__device__ unsigned int g_count = 0;

__global__ __launch_bounds__(THREADS, 1)
void chamfer_nn_kernel(const float* __restrict__ pred,
                       const float* __restrict__ targ,
                       float* __restrict__ out)
{
    extern __shared__ unsigned char dynsmem[];
    float4* shD  = (float4*)dynsmem;                              // sorted DB (x,y,x2+y2,0)
    float2* shQ  = (float2*)(dynsmem + SMEM_D_BYTES);             // sorted queries
    short*  shQi = (short*)(dynsmem + SMEM_D_BYTES + SMEM_Q_BYTES);

    __shared__ int   cntD[NBINS], cntQ[NBINS];     // histogram -> scatter cursors
    __shared__ int   offD[NBINS + 1];
    __shared__ float red[NWARPS];
    __shared__ int   lastflag;

    const int bx    = blockIdx.x;
    const int batch = bx >> 1;
    const int dir   = bx & 1;
    const int tid   = threadIdx.x;
    const int wg    = tid >> 5, lane = tid & 31;

    const float* q_base = (dir == 0 ? pred : targ) + batch * (2 * K);
    const float* d_base = (dir == 0 ? targ : pred) + batch * (2 * K);

    // ---- Load both sides (coalesced); fixed bucket range, no reductions ----
    float Dx[PPT], Dy[PPT], Qx[PPT], Qy[PPT];
    #pragma unroll
    for (int r = 0; r < PPT; ++r) {
        int j = r * THREADS + tid;
        Dx[r] = d_base[j];  Dy[r] = d_base[j + K];
        Qx[r] = q_base[j];  Qy[r] = q_base[j + K];
    }

    if (tid < NBINS) { cntD[tid] = 0; cntQ[tid] = 0; }
    __syncthreads();

    int bD[PPT], bQ[PPT];
    #pragma unroll
    for (int r = 0; r < PPT; ++r) {
        bD[r] = min(NBINS - 1, max(0, (int)((Dx[r] - XMIN) * INVW)));
        atomicAdd(&cntD[bD[r]], 1);
        bQ[r] = min(NBINS - 1, max(0, (int)((Qx[r] - XMIN) * INVW)));
        atomicAdd(&cntQ[bQ[r]], 1);
    }
    __syncthreads();

    // ---- Exclusive prefix over 256 bins (warp 0: D + offD; warp 1: Q) ----
    if (wg < 2) {
        int* cnt = (wg == 0) ? cntD : cntQ;
        int c[8], s = 0;
        #pragma unroll
        for (int i = 0; i < 8; ++i) { c[i] = cnt[lane * 8 + i]; s += c[i]; }
        int e = s;
        #pragma unroll
        for (int o = 1; o < 32; o <<= 1) {
            int n = __shfl_up_sync(0xFFFFFFFF, e, o);
            if (lane >= o) e += n;
        }
        int run = e - s;
        #pragma unroll
        for (int i = 0; i < 8; ++i) {
            if (wg == 0) offD[lane * 8 + i] = run;
            cnt[lane * 8 + i] = run;
            run += c[i];
        }
        if (wg == 0 && lane == 31) offD[NBINS] = e;   // = K
    }
    __syncthreads();

    // ---- Scatter into bucket order ----
    #pragma unroll
    for (int r = 0; r < PPT; ++r) {
        int p = atomicAdd(&cntD[bD[r]], 1);
        shD[p] = make_float4(Dx[r], Dy[r], fmaf(Dx[r], Dx[r], Dy[r] * Dy[r]), 0.0f);
        p = atomicAdd(&cntQ[bQ[r]], 1);
        shQ[p]  = make_float2(Qx[r], Qy[r]);
        shQi[p] = (short)(r * THREADS + tid);
    }
    __syncthreads();

    // ---- Scan: warp w handles groups w and 31-w (heavy+light pairing).
    //      Each group = 64 consecutive sorted queries, 2 per lane.         ----
    float  resv[2][2];
    short2 resi[2];
    #pragma unroll
    for (int pass = 0; pass < 2; ++pass) {
        const int g = pass ? (31 - wg) : wg;
        const int pairidx = g * 32 + lane;
        const float4 qq = *(const float4*)&shQ[2 * pairidx];
        resi[pass] = ((const short2*)shQi)[pairidx];

        const float ax0 = -2.0f * qq.x, ay0 = -2.0f * qq.y;
        const float ax1 = -2.0f * qq.z, ay1 = -2.0f * qq.w;
        const float q20 = fmaf(qq.x, qq.x, qq.y * qq.y);
        const float q21 = fmaf(qq.z, qq.z, qq.w * qq.w);
        const float qxmn = fminf(qq.x, qq.z);
        const float qxmx = fmaxf(qq.x, qq.z);

        int b0 = min(NBINS - 1, max(0, (int)((qq.x - XMIN) * INVW)));
        int b1 = min(NBINS - 1, max(0, (int)((qq.z - XMIN) * INVW)));
        const int bl = __reduce_min_sync(0xFFFFFFFF, min(b0, b1));
        const int bh = __reduce_max_sync(0xFFFFFFFF, max(b0, b1));

        float mnA0 = INFINITY, mnB0 = INFINITY;
        float mnA1 = INFINITY, mnB1 = INFINITY;

        // Phase 1: contiguous neighborhood, unroll 4 (4 LDS.128 in flight)
        {
            const int lo = offD[max(bl - 1, 0)];
            const int hi = offD[min(bh + 1, NBINS - 1) + 1];
            int idx = lo;
            for (; idx + 4 <= hi; idx += 4) {
                float4 t0 = shD[idx],     t1 = shD[idx + 1];
                float4 t2 = shD[idx + 2], t3 = shD[idx + 3];
                mnA0 = fminf(mnA0, fmaf(ax0, t0.x, fmaf(ay0, t0.y, t0.z)));
                mnA1 = fminf(mnA1, fmaf(ax1, t0.x, fmaf(ay1, t0.y, t0.z)));
                mnB0 = fminf(mnB0, fmaf(ax0, t1.x, fmaf(ay0, t1.y, t1.z)));
                mnB1 = fminf(mnB1, fmaf(ax1, t1.x, fmaf(ay1, t1.y, t1.z)));
                mnA0 = fminf(mnA0, fmaf(ax0, t2.x, fmaf(ay0, t2.y, t2.z)));
                mnA1 = fminf(mnA1, fmaf(ax1, t2.x, fmaf(ay1, t2.y, t2.z)));
                mnB0 = fminf(mnB0, fmaf(ax0, t3.x, fmaf(ay0, t3.y, t3.z)));
                mnB1 = fminf(mnB1, fmaf(ax1, t3.x, fmaf(ay1, t3.y, t3.z)));
            }
            for (; idx < hi; ++idx) {
                float4 t = shD[idx];
                mnA0 = fminf(mnA0, fmaf(ax0, t.x, fmaf(ay0, t.y, t.z)));
                mnA1 = fminf(mnA1, fmaf(ax1, t.x, fmaf(ay1, t.y, t.z)));
            }
        }

        // Left expansion: per-bucket warp vote.
        for (int l = bl - 2; l >= 0; --l) {
            float best = fmaxf(q20 + fminf(mnA0, mnB0), q21 + fminf(mnA1, mnB1));
            float gap  = qxmn - (XMIN + (float)(l + 1) * WB);
            bool need  = (gap <= 0.0f) || (gap * gap < best);
            if (!__any_sync(0xFFFFFFFF, need)) break;
            const int lo = offD[l], hi = offD[l + 1];
            for (int idx = lo; idx < hi; ++idx) {
                float4 t = shD[idx];
                mnA0 = fminf(mnA0, fmaf(ax0, t.x, fmaf(ay0, t.y, t.z)));
                mnA1 = fminf(mnA1, fmaf(ax1, t.x, fmaf(ay1, t.y, t.z)));
            }
        }
        // Right expansion.
        for (int r = bh + 2; r < NBINS; ++r) {
            float best = fmaxf(q20 + fminf(mnA0, mnB0), q21 + fminf(mnA1, mnB1));
            float gap  = (XMIN + (float)r * WB) - qxmx;
            bool need  = (gap <= 0.0f) || (gap * gap < best);
            if (!__any_sync(0xFFFFFFFF, need)) break;
            const int lo = offD[r], hi = offD[r + 1];
            for (int idx = lo; idx < hi; ++idx) {
                float4 t = shD[idx];
                mnB0 = fminf(mnB0, fmaf(ax0, t.x, fmaf(ay0, t.y, t.z)));
                mnB1 = fminf(mnB1, fmaf(ax1, t.x, fmaf(ay1, t.y, t.z)));
            }
        }

        resv[pass][0] = sqrtf(fmaxf(q20 + fminf(mnA0, mnB0), 0.0f));
        resv[pass][1] = sqrtf(fmaxf(q21 + fminf(mnA1, mnB1), 0.0f));
    }
    __syncthreads();     // all warps done reading shD/shQ before overwrite

    // ---- Scatter results to original order (reuse shD), fixed-order sum ----
    float* rslt = (float*)shD;
    rslt[resi[0].x] = resv[0][0];
    rslt[resi[0].y] = resv[0][1];
    rslt[resi[1].x] = resv[1][0];
    rslt[resi[1].y] = resv[1][1];
    __syncthreads();

    float s = 0.0f;
    #pragma unroll
    for (int r = 0; r < PPT; ++r)
        s += rslt[tid + r * THREADS];
    #pragma unroll
    for (int o = 16; o > 0; o >>= 1)
        s += __shfl_xor_sync(0xFFFFFFFF, s, o);
    if (lane == 0) red[wg] = s;
    __syncthreads();

    float v = 0.0f;
    if (tid < 32) {
        v = (tid < NWARPS) ? red[tid] : 0.0f;
        #pragma unroll
        for (int o = 8; o > 0; o >>= 1)
            v += __shfl_down_sync(0xFFFFFFFF, v, o);
    }

    // ---- Fused finalize: last block sums the 128 partials ----
    if (tid == 0) {
        g_partials[bx] = v;
        __threadfence();
        unsigned old = atomicAdd(&g_count, 1u);
        lastflag = (old == NBLOCKS - 1);
    }
    __syncthreads();
    if (lastflag && tid < 32) {
        volatile float* gp = g_partials;
        float t = 0.0f;
        #pragma unroll
        for (int i = 0; i < NBLOCKS / 32; ++i)
            t += gp[i * 32 + tid];
        #pragma unroll
        for (int o = 16; o > 0; o >>= 1)
            t += __shfl_down_sync(0xFFFFFFFF, t, o);
        if (tid == 0) {
            out[0] = t * (1.0f / ((float)K * (float)BATCH));
            g_count = 0;   // reset for next graph replay
        }
    }
}

extern "C" void kernel_launch(void* const* d_in, const int* in_sizes, int n_in,
                              void* d_out, int out_size)
{
    const float* pred = (const float*)d_in[0];
    const float* targ = (const float*)d_in[1];
    float* out = (float*)d_out;

    cudaFuncSetAttribute(chamfer_nn_kernel,
                         cudaFuncAttributeMaxDynamicSharedMemorySize, DYN_SMEM);
    chamfer_nn_kernel<<<NBLOCKS, THREADS, DYN_SMEM>>>(pred, targ, out);
}